// round 12
// baseline (speedup 1.0000x reference)
#include <cuda_runtime.h>
#include <cuda_fp16.h>

#define N_NODES 50000
#define N_EDGES 800000
#define NEG_SLOPE 0.2f
#define LN_EPS 1e-5f

// ---------------- scratch (no allocs allowed) ----------------
// node features in fp16: 16 x uint2 per node (each uint2 = 4 halves = 4 channels)
__device__ uint2 g_xlh[N_NODES * 16];      // xl = x@Wl + bl  (fp16 packed)
__device__ uint2 g_xrh[N_NODES * 16];      // xr = x@Wr + br  (fp16 packed)
__device__ float g_denom[N_NODES * 4];     // softmax denominators
__device__ float g_agg[N_NODES * 64];      // unnormalized aggregated messages (fp32)

__device__ __forceinline__ float4 unpackh4(uint2 u) {
    __half2 h0 = *reinterpret_cast<__half2*>(&u.x);
    __half2 h1 = *reinterpret_cast<__half2*>(&u.y);
    float2 f0 = __half22float2(h0);
    float2 f1 = __half22float2(h1);
    return make_float4(f0.x, f0.y, f1.x, f1.y);
}

__device__ __forceinline__ unsigned f2tf32(float f) {
    unsigned r;
    asm("cvt.rna.tf32.f32 %0, %1;" : "=r"(r) : "f"(f));
    return r;
}

__device__ __forceinline__ unsigned packh2(float a, float b) {
    __half2 h = __floats2half2_rn(a, b);
    return *reinterpret_cast<unsigned*>(&h);
}

// ---------------- K1: tf32 tensor-core dual GEMM + scratch zeroing ----------------
// 256 threads (8 warps), 128-node tile. smem: xs[64][136] + ws[64][136] tf32.
// Warp w computes rows m0=w*16 .. m0+15, all 128 output cols via 16 n-tiles of
// mma.m16n8k8, K = 8 k-steps. fp32 accumulate; epilogue packs fp16.
#define GEMM_TILE 128
#define SSTRIDE 136
#define GEMM_SMEM (2 * 64 * SSTRIDE * 4)   // 69632 B

__global__ __launch_bounds__(256, 2) void gemm_kernel(
    const float* __restrict__ x,
    const float* __restrict__ Wl, const float* __restrict__ bl,
    const float* __restrict__ Wr, const float* __restrict__ br)
{
    extern __shared__ __align__(16) unsigned smem_u[];
    unsigned* xs = smem_u;                 // [64][136] tf32 of x^T (k-major)
    unsigned* ws = smem_u + 64 * SSTRIDE;  // [64][136] tf32 of [Wl|Wr] (k-major)

    const int tid = threadIdx.x;
    const int node0 = blockIdx.x * GEMM_TILE;

    // ---- zero this tile's g_agg / g_denom ----
    {
        const float4 z4 = make_float4(0.f, 0.f, 0.f, 0.f);
#pragma unroll
        for (int i = 0; i < 8; i++) {
            int q = tid + i * 256;                 // float4 idx in tile (0..2047)
            int n = node0 + (q >> 4);
            if (n < N_NODES)
                ((float4*)g_agg)[(size_t)node0 * 16 + q] = z4;
        }
#pragma unroll
        for (int i = 0; i < 2; i++) {
            int q = tid + i * 256;
            int n = node0 + (q >> 2);
            if (n < N_NODES) g_denom[node0 * 4 + q] = 0.f;
        }
    }

    // ---- stage W concat: ws[k][n] = tf32( n<64 ? Wl[k][n] : Wr[k][n-64] ) ----
    for (int i = tid; i < 64 * 128; i += 256) {
        int k = i >> 7, n = i & 127;
        float v = (n < 64) ? __ldg(&Wl[k * 64 + n]) : __ldg(&Wr[k * 64 + (n - 64)]);
        ws[k * SSTRIDE + n] = f2tf32(v);
    }

    // ---- stage x transposed: xs[k][node_local] (tf32) ----
    for (int i4 = tid; i4 < GEMM_TILE * 16; i4 += 256) {
        int nl = i4 >> 4;
        int k4 = (i4 & 15) * 4;
        int n = node0 + nl;
        float4 v = (n < N_NODES) ? ((const float4*)x)[(size_t)n * 16 + (i4 & 15)]
                                 : make_float4(0.f, 0.f, 0.f, 0.f);
        xs[(k4 + 0) * SSTRIDE + nl] = f2tf32(v.x);
        xs[(k4 + 1) * SSTRIDE + nl] = f2tf32(v.y);
        xs[(k4 + 2) * SSTRIDE + nl] = f2tf32(v.z);
        xs[(k4 + 3) * SSTRIDE + nl] = f2tf32(v.w);
    }
    __syncthreads();

    const int warp = tid >> 5;
    const int laneid = tid & 31;
    const int gid = laneid >> 2;      // 0..7
    const int tig = laneid & 3;       // 0..3
    const int m0 = warp * 16;

    float acc[16][4];
#pragma unroll
    for (int t = 0; t < 16; t++)
#pragma unroll
        for (int j = 0; j < 4; j++) acc[t][j] = 0.f;

#pragma unroll
    for (int k0 = 0; k0 < 8; k0++) {
        const int kb = k0 * 8;
        // A fragments (m16 x k8): a0:(gid,tig) a1:(gid+8,tig) a2:(gid,tig+4) a3:(gid+8,tig+4)
        unsigned a0 = xs[(kb + tig) * SSTRIDE + m0 + gid];
        unsigned a1 = xs[(kb + tig) * SSTRIDE + m0 + gid + 8];
        unsigned a2 = xs[(kb + tig + 4) * SSTRIDE + m0 + gid];
        unsigned a3 = xs[(kb + tig + 4) * SSTRIDE + m0 + gid + 8];
#pragma unroll
        for (int t = 0; t < 16; t++) {
            // B fragments (k8 x n8): b0:(tig, gid) b1:(tig+4, gid)
            unsigned b0 = ws[(kb + tig) * SSTRIDE + t * 8 + gid];
            unsigned b1 = ws[(kb + tig + 4) * SSTRIDE + t * 8 + gid];
            asm volatile(
                "mma.sync.aligned.m16n8k8.row.col.f32.tf32.tf32.f32 "
                "{%0,%1,%2,%3}, {%4,%5,%6,%7}, {%8,%9}, {%0,%1,%2,%3};"
                : "+f"(acc[t][0]), "+f"(acc[t][1]), "+f"(acc[t][2]), "+f"(acc[t][3])
                : "r"(a0), "r"(a1), "r"(a2), "r"(a3), "r"(b0), "r"(b1));
        }
    }

    // ---- epilogue: +bias, pack fp16, store ----
    // c0:(gid,2tig) c1:(gid,2tig+1) c2:(gid+8,2tig) c3:(gid+8,2tig+1) per n-tile
    const int r0 = node0 + m0 + gid;
    const int r1 = r0 + 8;
    unsigned* xl_u = (unsigned*)g_xlh;
    unsigned* xr_u = (unsigned*)g_xrh;

#pragma unroll
    for (int t = 0; t < 16; t++) {
        const int c = (t & 7) * 8 + tig * 2;       // col within the 64-wide half
        const bool isL = (t < 8);
        float2 bv = isL ? __ldg((const float2*)&bl[c])
                        : __ldg((const float2*)&br[c]);
        unsigned w0 = packh2(acc[t][0] + bv.x, acc[t][1] + bv.y);
        unsigned w1 = packh2(acc[t][2] + bv.x, acc[t][3] + bv.y);
        unsigned* base = isL ? xl_u : xr_u;
        const int widx = c >> 1;                   // half2 word within 32-word row
        if (r0 < N_NODES) base[(size_t)r0 * 32 + widx] = w0;
        if (r1 < N_NODES) base[(size_t)r1 * 32 + widx] = w1;
    }
}

__device__ __forceinline__ float lrelu(float v) {
    return v > 0.f ? v : NEG_SLOPE * v;
}

// ---------------- K2: FUSED edge pass, 2 edges per half-warp, fp16 gathers ----------------
__global__ __launch_bounds__(256) void edge_kernel(
    const int* __restrict__ ei, const float* __restrict__ att)
{
    const int tid = threadIdx.x;
    const int lane = tid & 31;
    const int half_ = lane >> 4;
    const int l16 = lane & 15;
    const int e0 = blockIdx.x * 32 + (tid >> 5) * 4 + half_ * 2;

    const int src0 = __ldg(&ei[e0]);
    const int dst0 = __ldg(&ei[N_EDGES + e0]);
    const int src1 = __ldg(&ei[e0 + 1]);
    const int dst1 = __ldg(&ei[N_EDGES + e0 + 1]);

    uint2 ua0 = __ldg(&g_xlh[(size_t)src0 * 16 + l16]);
    uint2 ub0 = __ldg(&g_xrh[(size_t)dst0 * 16 + l16]);
    uint2 ua1 = __ldg(&g_xlh[(size_t)src1 * 16 + l16]);
    uint2 ub1 = __ldg(&g_xrh[(size_t)dst1 * 16 + l16]);
    float4 av = __ldg(&((const float4*)att)[l16]);

    float4 a0 = unpackh4(ua0), b0 = unpackh4(ub0);
    float4 a1 = unpackh4(ua1), b1 = unpackh4(ub1);

    float s0 = lrelu(a0.x + b0.x) * av.x + lrelu(a0.y + b0.y) * av.y +
               lrelu(a0.z + b0.z) * av.z + lrelu(a0.w + b0.w) * av.w;
    float s1 = lrelu(a1.x + b1.x) * av.x + lrelu(a1.y + b1.y) * av.y +
               lrelu(a1.z + b1.z) * av.z + lrelu(a1.w + b1.w) * av.w;

    s0 += __shfl_xor_sync(0xffffffffu, s0, 1);
    s0 += __shfl_xor_sync(0xffffffffu, s0, 2);
    s1 += __shfl_xor_sync(0xffffffffu, s1, 1);
    s1 += __shfl_xor_sync(0xffffffffu, s1, 2);

    const float p0 = __expf(s0);
    const float p1 = __expf(s1);

    float* dp0 = &g_agg[(size_t)dst0 * 64 + l16 * 4];
    asm volatile("red.global.add.v4.f32 [%0], {%1,%2,%3,%4};"
                 :: "l"(dp0), "f"(p0 * a0.x), "f"(p0 * a0.y), "f"(p0 * a0.z), "f"(p0 * a0.w)
                 : "memory");
    float* dp1 = &g_agg[(size_t)dst1 * 64 + l16 * 4];
    asm volatile("red.global.add.v4.f32 [%0], {%1,%2,%3,%4};"
                 :: "l"(dp1), "f"(p1 * a1.x), "f"(p1 * a1.y), "f"(p1 * a1.z), "f"(p1 * a1.w)
                 : "memory");

    if ((l16 & 3) == 0) {
        const int h = l16 >> 2;
        atomicAdd(&g_denom[(size_t)dst0 * 4 + h], p0);
        atomicAdd(&g_denom[(size_t)dst1 * 4 + h], p1);
    }
}

// ---------------- K3: normalize + residual + LayerNorm + ELU ----------------
__global__ __launch_bounds__(256) void finalize_kernel(
    const float* __restrict__ x, const float* __restrict__ bias,
    const float* __restrict__ gamma, const float* __restrict__ beta,
    float* __restrict__ out)
{
    const int tid = threadIdx.x;
    const int lane = tid & 31;
    const int half_ = lane >> 4;
    const int l16 = lane & 15;
    const int n = blockIdx.x * 16 + (tid >> 5) * 2 + half_;

    float4 o = ((const float4*)g_agg)[n * 16 + l16];
    float den = g_denom[n * 4 + (l16 >> 2)];
    float inv_den = __fdividef(1.f, den);

    float4 xv = ((const float4*)x)[n * 16 + l16];
    float4 bv = __ldg(&((const float4*)bias)[l16]);

    float c0 = fmaf(o.x, inv_den, xv.x + bv.x);
    float c1 = fmaf(o.y, inv_den, xv.y + bv.y);
    float c2 = fmaf(o.z, inv_den, xv.z + bv.z);
    float c3 = fmaf(o.w, inv_den, xv.w + bv.w);

    float sum = c0 + c1 + c2 + c3;
    float sq = c0 * c0 + c1 * c1 + c2 * c2 + c3 * c3;
#pragma unroll
    for (int off = 8; off > 0; off >>= 1) {
        sum += __shfl_xor_sync(0xffffffff, sum, off);
        sq += __shfl_xor_sync(0xffffffff, sq, off);
    }
    float mean = sum * (1.f / 64.f);
    float var = sq * (1.f / 64.f) - mean * mean;
    float inv = rsqrtf(var + LN_EPS);

    float4 gv = __ldg(&((const float4*)gamma)[l16]);
    float4 be = __ldg(&((const float4*)beta)[l16]);

    float y0 = (c0 - mean) * inv * gv.x + be.x;
    float y1 = (c1 - mean) * inv * gv.y + be.y;
    float y2 = (c2 - mean) * inv * gv.z + be.z;
    float y3 = (c3 - mean) * inv * gv.w + be.w;
    y0 = y0 > 0.f ? y0 : expm1f(y0);
    y1 = y1 > 0.f ? y1 : expm1f(y1);
    y2 = y2 > 0.f ? y2 : expm1f(y2);
    y3 = y3 > 0.f ? y3 : expm1f(y3);

    float4 r; r.x = y0; r.y = y1; r.z = y2; r.w = y3;
    ((float4*)out)[n * 16 + l16] = r;
}

// ---------------- launch ----------------
extern "C" void kernel_launch(void* const* d_in, const int* in_sizes, int n_in,
                              void* d_out, int out_size)
{
    const float* x     = (const float*)d_in[0];
    const int*   ei    = (const int*)d_in[1];
    const float* Wl    = (const float*)d_in[2];
    const float* bl    = (const float*)d_in[3];
    const float* Wr    = (const float*)d_in[4];
    const float* br    = (const float*)d_in[5];
    const float* att   = (const float*)d_in[6];
    const float* bias  = (const float*)d_in[7];
    const float* gamma = (const float*)d_in[8];
    const float* beta  = (const float*)d_in[9];
    float* out = (float*)d_out;

    cudaFuncSetAttribute(gemm_kernel,
                         cudaFuncAttributeMaxDynamicSharedMemorySize, GEMM_SMEM);

    gemm_kernel<<<(N_NODES + GEMM_TILE - 1) / GEMM_TILE, 256, GEMM_SMEM>>>(
        x, Wl, bl, Wr, br);
    edge_kernel<<<N_EDGES / 32, 256>>>(ei, att);
    finalize_kernel<<<N_NODES / 16, 256>>>(x, bias, gamma, beta, out);
}

// round 14
// speedup vs baseline: 1.1910x; 1.1910x over previous
#include <cuda_runtime.h>
#include <cuda_fp16.h>

#define N_NODES 50000
#define N_EDGES 800000
#define NEG_SLOPE 0.2f
#define LN_EPS 1e-5f

// ---------------- scratch (no allocs allowed) ----------------
// node features / aggregates in fp16: 16 x uint2 per node (uint2 = 4 halves)
__device__ uint2 g_xlh[N_NODES * 16];      // xl = x@Wl + bl  (fp16 packed)
__device__ uint2 g_xrh[N_NODES * 16];      // xr = x@Wr + br  (fp16 packed)
__device__ uint2 g_aggh[N_NODES * 16];     // unnormalized aggregated messages (fp16)
__device__ float g_denom[N_NODES * 4];     // softmax denominators (fp32)

__device__ __forceinline__ uint2 packh4(float a, float b, float c, float d) {
    __half2 h0 = __floats2half2_rn(a, b);
    __half2 h1 = __floats2half2_rn(c, d);
    uint2 u;
    u.x = *reinterpret_cast<unsigned int*>(&h0);
    u.y = *reinterpret_cast<unsigned int*>(&h1);
    return u;
}

__device__ __forceinline__ unsigned packh2(float a, float b) {
    __half2 h = __floats2half2_rn(a, b);
    return *reinterpret_cast<unsigned*>(&h);
}

__device__ __forceinline__ float4 unpackh4(uint2 u) {
    __half2 h0 = *reinterpret_cast<__half2*>(&u.x);
    __half2 h1 = *reinterpret_cast<__half2*>(&u.y);
    float2 f0 = __half22float2(h0);
    float2 f1 = __half22float2(h1);
    return make_float4(f0.x, f0.y, f1.x, f1.y);
}

// ---------------- K1: fused dual GEMM (SIMT fp32) + scratch zeroing ----------------
// 256 threads, 64-node tile, 4 blocks/SM. dynamic smem 50176 B.
#define GEMM_TILE 64
#define XT_STRIDE 68
#define GEMM_SMEM ((64 * XT_STRIDE + 2 * 4096) * 4)   // 50176 B

__global__ __launch_bounds__(256, 4) void gemm_kernel(
    const float* __restrict__ x,
    const float* __restrict__ Wl, const float* __restrict__ bl,
    const float* __restrict__ Wr, const float* __restrict__ br)
{
    extern __shared__ __align__(16) float smem[];
    float* xT  = smem;                     // 64*68 floats
    float* Wls = smem + 64 * XT_STRIDE;    // 4096
    float* Wrs = Wls + 4096;               // 4096

    const int tid = threadIdx.x;
    const int node0 = blockIdx.x * GEMM_TILE;

    // ---- zero this tile's g_aggh / g_denom ----
    {
        const uint4 z4 = make_uint4(0u, 0u, 0u, 0u);
#pragma unroll
        for (int i = 0; i < 2; i++) {
            int q = tid + i * 256;                 // uint4 idx within tile (0..511)
            int n = node0 + (q >> 3);              // 8 uint4 per node
            if (n < N_NODES)
                ((uint4*)g_aggh)[(size_t)node0 * 8 + q] = z4;
        }
        int n = node0 + (tid >> 2);
        if (n < N_NODES) g_denom[node0 * 4 + tid] = 0.f;
    }

    // ---- stage W (float4, coalesced) ----
#pragma unroll
    for (int i = tid; i < 1024; i += 256) {
        ((float4*)Wls)[i] = __ldg(&((const float4*)Wl)[i]);
        ((float4*)Wrs)[i] = __ldg(&((const float4*)Wr)[i]);
    }

    // ---- stage x transposed: xT[k][node_local] ----
    for (int i4 = tid; i4 < GEMM_TILE * 16; i4 += 256) {
        int nl = i4 >> 4;
        int k4 = (i4 & 15) * 4;
        int n = node0 + nl;
        float4 v = (n < N_NODES) ? ((const float4*)x)[(size_t)n * 16 + (i4 & 15)]
                                 : make_float4(0.f, 0.f, 0.f, 0.f);
        xT[(k4 + 0) * XT_STRIDE + nl] = v.x;
        xT[(k4 + 1) * XT_STRIDE + nl] = v.y;
        xT[(k4 + 2) * XT_STRIDE + nl] = v.z;
        xT[(k4 + 3) * XT_STRIDE + nl] = v.w;
    }
    __syncthreads();

    const int dq = (tid & 15) * 4;   // output col base
    const int nq = (tid >> 4) * 4;   // local node base

    float accl[4][4] = {{0.f}}, accr[4][4] = {{0.f}};

#pragma unroll 4
    for (int k = 0; k < 64; k++) {
        float4 xv = *(const float4*)&xT[k * XT_STRIDE + nq];
        float4 wl = *(const float4*)&Wls[k * 64 + dq];
        float4 wr = *(const float4*)&Wrs[k * 64 + dq];
        float xa[4] = {xv.x, xv.y, xv.z, xv.w};
        float wla[4] = {wl.x, wl.y, wl.z, wl.w};
        float wra[4] = {wr.x, wr.y, wr.z, wr.w};
#pragma unroll
        for (int i = 0; i < 4; i++)
#pragma unroll
            for (int j = 0; j < 4; j++) {
                accl[i][j] = fmaf(xa[i], wla[j], accl[i][j]);
                accr[i][j] = fmaf(xa[i], wra[j], accr[i][j]);
            }
    }

    float4 blv = *(const float4*)&bl[dq];
    float4 brv = *(const float4*)&br[dq];

#pragma unroll
    for (int i = 0; i < 4; i++) {
        int n = node0 + nq + i;
        if (n < N_NODES) {
            g_xlh[(size_t)n * 16 + (dq >> 2)] = packh4(
                accl[i][0] + blv.x, accl[i][1] + blv.y,
                accl[i][2] + blv.z, accl[i][3] + blv.w);
            g_xrh[(size_t)n * 16 + (dq >> 2)] = packh4(
                accr[i][0] + brv.x, accr[i][1] + brv.y,
                accr[i][2] + brv.z, accr[i][3] + brv.w);
        }
    }
}

__device__ __forceinline__ float lrelu(float v) {
    return v > 0.f ? v : NEG_SLOPE * v;
}

// ---------------- K2: FUSED edge pass, 2 edges per half-warp ----------------
// fp16 gathers (8 B/lane) and fp16x2 vector REDs (8 B/lane). 800000 % 32 == 0.
__global__ __launch_bounds__(256) void edge_kernel(
    const int* __restrict__ ei, const float* __restrict__ att)
{
    const int tid = threadIdx.x;
    const int lane = tid & 31;
    const int half_ = lane >> 4;
    const int l16 = lane & 15;
    const int e0 = blockIdx.x * 32 + (tid >> 5) * 4 + half_ * 2;

    const int src0 = __ldg(&ei[e0]);
    const int dst0 = __ldg(&ei[N_EDGES + e0]);
    const int src1 = __ldg(&ei[e0 + 1]);
    const int dst1 = __ldg(&ei[N_EDGES + e0 + 1]);

    uint2 ua0 = __ldg(&g_xlh[(size_t)src0 * 16 + l16]);
    uint2 ub0 = __ldg(&g_xrh[(size_t)dst0 * 16 + l16]);
    uint2 ua1 = __ldg(&g_xlh[(size_t)src1 * 16 + l16]);
    uint2 ub1 = __ldg(&g_xrh[(size_t)dst1 * 16 + l16]);
    float4 av = __ldg(&((const float4*)att)[l16]);

    float4 a0 = unpackh4(ua0), b0 = unpackh4(ub0);
    float4 a1 = unpackh4(ua1), b1 = unpackh4(ub1);

    float s0 = lrelu(a0.x + b0.x) * av.x + lrelu(a0.y + b0.y) * av.y +
               lrelu(a0.z + b0.z) * av.z + lrelu(a0.w + b0.w) * av.w;
    float s1 = lrelu(a1.x + b1.x) * av.x + lrelu(a1.y + b1.y) * av.y +
               lrelu(a1.z + b1.z) * av.z + lrelu(a1.w + b1.w) * av.w;

    s0 += __shfl_xor_sync(0xffffffffu, s0, 1);
    s0 += __shfl_xor_sync(0xffffffffu, s0, 2);
    s1 += __shfl_xor_sync(0xffffffffu, s1, 1);
    s1 += __shfl_xor_sync(0xffffffffu, s1, 2);

    const float p0 = __expf(s0);
    const float p1 = __expf(s1);

    unsigned u00 = packh2(p0 * a0.x, p0 * a0.y);
    unsigned u01 = packh2(p0 * a0.z, p0 * a0.w);
    unsigned u10 = packh2(p1 * a1.x, p1 * a1.y);
    unsigned u11 = packh2(p1 * a1.z, p1 * a1.w);

    uint2* dp0 = &g_aggh[(size_t)dst0 * 16 + l16];
    asm volatile("red.global.add.noftz.v2.f16x2 [%0], {%1,%2};"
                 :: "l"(dp0), "r"(u00), "r"(u01) : "memory");
    uint2* dp1 = &g_aggh[(size_t)dst1 * 16 + l16];
    asm volatile("red.global.add.noftz.v2.f16x2 [%0], {%1,%2};"
                 :: "l"(dp1), "r"(u10), "r"(u11) : "memory");

    if ((l16 & 3) == 0) {
        const int h = l16 >> 2;
        atomicAdd(&g_denom[(size_t)dst0 * 4 + h], p0);
        atomicAdd(&g_denom[(size_t)dst1 * 4 + h], p1);
    }
}

// ---------------- K3: normalize + residual + LayerNorm + ELU ----------------
__global__ __launch_bounds__(256) void finalize_kernel(
    const float* __restrict__ x, const float* __restrict__ bias,
    const float* __restrict__ gamma, const float* __restrict__ beta,
    float* __restrict__ out)
{
    const int tid = threadIdx.x;
    const int lane = tid & 31;
    const int half_ = lane >> 4;
    const int l16 = lane & 15;
    const int n = blockIdx.x * 16 + (tid >> 5) * 2 + half_;

    float4 o = unpackh4(g_aggh[(size_t)n * 16 + l16]);
    float den = g_denom[n * 4 + (l16 >> 2)];
    float inv_den = __fdividef(1.f, den);

    float4 xv = ((const float4*)x)[n * 16 + l16];
    float4 bv = __ldg(&((const float4*)bias)[l16]);

    float c0 = fmaf(o.x, inv_den, xv.x + bv.x);
    float c1 = fmaf(o.y, inv_den, xv.y + bv.y);
    float c2 = fmaf(o.z, inv_den, xv.z + bv.z);
    float c3 = fmaf(o.w, inv_den, xv.w + bv.w);

    float sum = c0 + c1 + c2 + c3;
    float sq = c0 * c0 + c1 * c1 + c2 * c2 + c3 * c3;
#pragma unroll
    for (int off = 8; off > 0; off >>= 1) {
        sum += __shfl_xor_sync(0xffffffff, sum, off);
        sq += __shfl_xor_sync(0xffffffff, sq, off);
    }
    float mean = sum * (1.f / 64.f);
    float var = sq * (1.f / 64.f) - mean * mean;
    float inv = rsqrtf(var + LN_EPS);

    float4 gv = __ldg(&((const float4*)gamma)[l16]);
    float4 be = __ldg(&((const float4*)beta)[l16]);

    float y0 = (c0 - mean) * inv * gv.x + be.x;
    float y1 = (c1 - mean) * inv * gv.y + be.y;
    float y2 = (c2 - mean) * inv * gv.z + be.z;
    float y3 = (c3 - mean) * inv * gv.w + be.w;
    y0 = y0 > 0.f ? y0 : (__expf(y0) - 1.f);
    y1 = y1 > 0.f ? y1 : (__expf(y1) - 1.f);
    y2 = y2 > 0.f ? y2 : (__expf(y2) - 1.f);
    y3 = y3 > 0.f ? y3 : (__expf(y3) - 1.f);

    float4 r; r.x = y0; r.y = y1; r.z = y2; r.w = y3;
    ((float4*)out)[n * 16 + l16] = r;
}

// ---------------- launch ----------------
extern "C" void kernel_launch(void* const* d_in, const int* in_sizes, int n_in,
                              void* d_out, int out_size)
{
    const float* x     = (const float*)d_in[0];
    const int*   ei    = (const int*)d_in[1];
    const float* Wl    = (const float*)d_in[2];
    const float* bl    = (const float*)d_in[3];
    const float* Wr    = (const float*)d_in[4];
    const float* br    = (const float*)d_in[5];
    const float* att   = (const float*)d_in[6];
    const float* bias  = (const float*)d_in[7];
    const float* gamma = (const float*)d_in[8];
    const float* beta  = (const float*)d_in[9];
    float* out = (float*)d_out;

    cudaFuncSetAttribute(gemm_kernel,
                         cudaFuncAttributeMaxDynamicSharedMemorySize, GEMM_SMEM);

    gemm_kernel<<<(N_NODES + GEMM_TILE - 1) / GEMM_TILE, 256, GEMM_SMEM>>>(
        x, Wl, bl, Wr, br);
    edge_kernel<<<N_EDGES / 32, 256>>>(ei, att);
    finalize_kernel<<<N_NODES / 16, 256>>>(x, bias, gamma, beta, out);
}

// round 17
// speedup vs baseline: 1.2058x; 1.0124x over previous
#include <cuda_runtime.h>
#include <cuda_fp16.h>
#include <cstdint>

#define N_NODES 50000
#define N_EDGES 800000
#define NEG_SLOPE 0.2f
#define LN_EPS 1e-5f

// ---------------- scratch (no allocs allowed) ----------------
__device__ uint2 g_xlh[N_NODES * 16];      // xl = x@Wl + bl  (fp16 packed, 4 ch per uint2)
__device__ uint2 g_xrh[N_NODES * 16];      // xr = x@Wr + br  (fp16 packed)
__device__ uint2 g_aggh[N_NODES * 16];     // unnormalized aggregated messages (fp16)
__device__ float g_denom[N_NODES * 4];     // softmax denominators (fp32)

__device__ __forceinline__ unsigned packh2(float a, float b) {
    __half2 h = __floats2half2_rn(a, b);
    return *reinterpret_cast<unsigned*>(&h);
}

__device__ __forceinline__ float4 unpackh4(uint2 u) {
    __half2 h0 = *reinterpret_cast<__half2*>(&u.x);
    __half2 h1 = *reinterpret_cast<__half2*>(&u.y);
    float2 f0 = __half22float2(h0);
    float2 f1 = __half22float2(h1);
    return make_float4(f0.x, f0.y, f1.x, f1.y);
}

// ---------------- packed f32x2 helpers ----------------
__device__ __forceinline__ unsigned long long pack2(float lo, float hi) {
    unsigned long long r;
    asm("mov.b64 %0, {%1,%2};" : "=l"(r) : "f"(lo), "f"(hi));
    return r;
}
__device__ __forceinline__ float2 unpack2(unsigned long long v) {
    float lo, hi;
    asm("mov.b64 {%0,%1}, %2;" : "=f"(lo), "=f"(hi) : "l"(v));
    return make_float2(lo, hi);
}
__device__ __forceinline__ void fma2(unsigned long long& d, unsigned long long a,
                                     unsigned long long b) {
    asm("fma.rn.f32x2 %0, %1, %2, %0;" : "+l"(d) : "l"(a), "l"(b));
}

// ---------------- K1: fused dual GEMM (FFMA2) + scratch zeroing ----------------
// 256 threads, 64-node tile, 4 blocks/SM. dynamic smem 50176 B.
// Each thread: 4 nodes x 4 cols x both matrices = 16 packed f32x2 accumulators.
#define GEMM_TILE 64
#define XT_STRIDE 68
#define GEMM_SMEM ((64 * XT_STRIDE + 2 * 4096) * 4)   // 50176 B

__global__ __launch_bounds__(256, 4) void gemm_kernel(
    const float* __restrict__ x,
    const float* __restrict__ Wl, const float* __restrict__ bl,
    const float* __restrict__ Wr, const float* __restrict__ br)
{
    extern __shared__ __align__(16) float smem[];
    float* xT  = smem;                     // 64*68 floats
    float* Wls = smem + 64 * XT_STRIDE;    // 4096
    float* Wrs = Wls + 4096;               // 4096

    const int tid = threadIdx.x;
    const int node0 = blockIdx.x * GEMM_TILE;

    // ---- zero this tile's g_aggh / g_denom ----
    {
        const uint4 z4 = make_uint4(0u, 0u, 0u, 0u);
#pragma unroll
        for (int i = 0; i < 2; i++) {
            int q = tid + i * 256;                 // uint4 idx within tile (0..511)
            int n = node0 + (q >> 3);              // 8 uint4 per node
            if (n < N_NODES)
                ((uint4*)g_aggh)[(size_t)node0 * 8 + q] = z4;
        }
        int n = node0 + (tid >> 2);
        if (n < N_NODES) g_denom[node0 * 4 + tid] = 0.f;
    }

    // ---- stage W (float4, coalesced) ----
#pragma unroll
    for (int i = tid; i < 1024; i += 256) {
        ((float4*)Wls)[i] = __ldg(&((const float4*)Wl)[i]);
        ((float4*)Wrs)[i] = __ldg(&((const float4*)Wr)[i]);
    }

    // ---- stage x transposed: xT[k][node_local] ----
    for (int i4 = tid; i4 < GEMM_TILE * 16; i4 += 256) {
        int nl = i4 >> 4;
        int k4 = (i4 & 15) * 4;
        int n = node0 + nl;
        float4 v = (n < N_NODES) ? ((const float4*)x)[(size_t)n * 16 + (i4 & 15)]
                                 : make_float4(0.f, 0.f, 0.f, 0.f);
        xT[(k4 + 0) * XT_STRIDE + nl] = v.x;
        xT[(k4 + 1) * XT_STRIDE + nl] = v.y;
        xT[(k4 + 2) * XT_STRIDE + nl] = v.z;
        xT[(k4 + 3) * XT_STRIDE + nl] = v.w;
    }
    __syncthreads();

    const int dq = (tid & 15) * 4;   // output col base
    const int nq = (tid >> 4) * 4;   // local node base

    // packed accumulators: [node][colpair] for L and R
    unsigned long long accl[4][2], accr[4][2];
#pragma unroll
    for (int i = 0; i < 4; i++) {
        accl[i][0] = accl[i][1] = pack2(0.f, 0.f);
        accr[i][0] = accr[i][1] = pack2(0.f, 0.f);
    }

#pragma unroll 4
    for (int k = 0; k < 64; k++) {
        float4 xv = *(const float4*)&xT[k * XT_STRIDE + nq];
        float4 wl = *(const float4*)&Wls[k * 64 + dq];
        float4 wr = *(const float4*)&Wrs[k * 64 + dq];
        unsigned long long wl0 = pack2(wl.x, wl.y), wl1 = pack2(wl.z, wl.w);
        unsigned long long wr0 = pack2(wr.x, wr.y), wr1 = pack2(wr.z, wr.w);
        float xa[4] = {xv.x, xv.y, xv.z, xv.w};
#pragma unroll
        for (int i = 0; i < 4; i++) {
            unsigned long long xx = pack2(xa[i], xa[i]);
            fma2(accl[i][0], xx, wl0);
            fma2(accl[i][1], xx, wl1);
            fma2(accr[i][0], xx, wr0);
            fma2(accr[i][1], xx, wr1);
        }
    }

    float4 blv = *(const float4*)&bl[dq];
    float4 brv = *(const float4*)&br[dq];

#pragma unroll
    for (int i = 0; i < 4; i++) {
        int n = node0 + nq + i;
        if (n < N_NODES) {
            float2 l0 = unpack2(accl[i][0]), l1 = unpack2(accl[i][1]);
            float2 r0 = unpack2(accr[i][0]), r1 = unpack2(accr[i][1]);
            uint2 ul, ur;
            ul.x = packh2(l0.x + blv.x, l0.y + blv.y);
            ul.y = packh2(l1.x + blv.z, l1.y + blv.w);
            ur.x = packh2(r0.x + brv.x, r0.y + brv.y);
            ur.y = packh2(r1.x + brv.z, r1.y + brv.w);
            g_xlh[(size_t)n * 16 + (dq >> 2)] = ul;
            g_xrh[(size_t)n * 16 + (dq >> 2)] = ur;
        }
    }
}

__device__ __forceinline__ float lrelu(float v) {
    return v > 0.f ? v : NEG_SLOPE * v;
}

// ---------------- K2: FUSED edge pass, 2 edges per half-warp ----------------
// fp16 gathers (8 B/lane) and fp16x2 vector REDs (8 B/lane). 800000 % 32 == 0.
__global__ __launch_bounds__(256) void edge_kernel(
    const int* __restrict__ ei, const float* __restrict__ att)
{
    const int tid = threadIdx.x;
    const int lane = tid & 31;
    const int half_ = lane >> 4;
    const int l16 = lane & 15;
    const int e0 = blockIdx.x * 32 + (tid >> 5) * 4 + half_ * 2;

    const int src0 = __ldg(&ei[e0]);
    const int dst0 = __ldg(&ei[N_EDGES + e0]);
    const int src1 = __ldg(&ei[e0 + 1]);
    const int dst1 = __ldg(&ei[N_EDGES + e0 + 1]);

    uint2 ua0 = __ldg(&g_xlh[(size_t)src0 * 16 + l16]);
    uint2 ub0 = __ldg(&g_xrh[(size_t)dst0 * 16 + l16]);
    uint2 ua1 = __ldg(&g_xlh[(size_t)src1 * 16 + l16]);
    uint2 ub1 = __ldg(&g_xrh[(size_t)dst1 * 16 + l16]);
    float4 av = __ldg(&((const float4*)att)[l16]);

    float4 a0 = unpackh4(ua0), b0 = unpackh4(ub0);
    float4 a1 = unpackh4(ua1), b1 = unpackh4(ub1);

    float s0 = lrelu(a0.x + b0.x) * av.x + lrelu(a0.y + b0.y) * av.y +
               lrelu(a0.z + b0.z) * av.z + lrelu(a0.w + b0.w) * av.w;
    float s1 = lrelu(a1.x + b1.x) * av.x + lrelu(a1.y + b1.y) * av.y +
               lrelu(a1.z + b1.z) * av.z + lrelu(a1.w + b1.w) * av.w;

    s0 += __shfl_xor_sync(0xffffffffu, s0, 1);
    s0 += __shfl_xor_sync(0xffffffffu, s0, 2);
    s1 += __shfl_xor_sync(0xffffffffu, s1, 1);
    s1 += __shfl_xor_sync(0xffffffffu, s1, 2);

    const float p0 = __expf(s0);
    const float p1 = __expf(s1);

    unsigned u00 = packh2(p0 * a0.x, p0 * a0.y);
    unsigned u01 = packh2(p0 * a0.z, p0 * a0.w);
    unsigned u10 = packh2(p1 * a1.x, p1 * a1.y);
    unsigned u11 = packh2(p1 * a1.z, p1 * a1.w);

    uint2* dp0 = &g_aggh[(size_t)dst0 * 16 + l16];
    asm volatile("red.global.add.noftz.v2.f16x2 [%0], {%1,%2};"
                 :: "l"(dp0), "r"(u00), "r"(u01) : "memory");
    uint2* dp1 = &g_aggh[(size_t)dst1 * 16 + l16];
    asm volatile("red.global.add.noftz.v2.f16x2 [%0], {%1,%2};"
                 :: "l"(dp1), "r"(u10), "r"(u11) : "memory");

    if ((l16 & 3) == 0) {
        const int h = l16 >> 2;
        atomicAdd(&g_denom[(size_t)dst0 * 4 + h], p0);
        atomicAdd(&g_denom[(size_t)dst1 * 4 + h], p1);
    }
}

// ---------------- K3: normalize + residual + LayerNorm + ELU ----------------
__global__ __launch_bounds__(256) void finalize_kernel(
    const float* __restrict__ x, const float* __restrict__ bias,
    const float* __restrict__ gamma, const float* __restrict__ beta,
    float* __restrict__ out)
{
    const int tid = threadIdx.x;
    const int lane = tid & 31;
    const int half_ = lane >> 4;
    const int l16 = lane & 15;
    const int n = blockIdx.x * 16 + (tid >> 5) * 2 + half_;

    float4 o = unpackh4(g_aggh[(size_t)n * 16 + l16]);
    float den = g_denom[n * 4 + (l16 >> 2)];
    float inv_den = __fdividef(1.f, den);

    float4 xv = ((const float4*)x)[n * 16 + l16];
    float4 bv = __ldg(&((const float4*)bias)[l16]);

    float c0 = fmaf(o.x, inv_den, xv.x + bv.x);
    float c1 = fmaf(o.y, inv_den, xv.y + bv.y);
    float c2 = fmaf(o.z, inv_den, xv.z + bv.z);
    float c3 = fmaf(o.w, inv_den, xv.w + bv.w);

    float sum = c0 + c1 + c2 + c3;
    float sq = c0 * c0 + c1 * c1 + c2 * c2 + c3 * c3;
#pragma unroll
    for (int off = 8; off > 0; off >>= 1) {
        sum += __shfl_xor_sync(0xffffffff, sum, off);
        sq += __shfl_xor_sync(0xffffffff, sq, off);
    }
    float mean = sum * (1.f / 64.f);
    float var = sq * (1.f / 64.f) - mean * mean;
    float inv = rsqrtf(var + LN_EPS);

    float4 gv = __ldg(&((const float4*)gamma)[l16]);
    float4 be = __ldg(&((const float4*)beta)[l16]);

    float y0 = (c0 - mean) * inv * gv.x + be.x;
    float y1 = (c1 - mean) * inv * gv.y + be.y;
    float y2 = (c2 - mean) * inv * gv.z + be.z;
    float y3 = (c3 - mean) * inv * gv.w + be.w;
    y0 = y0 > 0.f ? y0 : (__expf(y0) - 1.f);
    y1 = y1 > 0.f ? y1 : (__expf(y1) - 1.f);
    y2 = y2 > 0.f ? y2 : (__expf(y2) - 1.f);
    y3 = y3 > 0.f ? y3 : (__expf(y3) - 1.f);

    float4 r; r.x = y0; r.y = y1; r.z = y2; r.w = y3;
    ((float4*)out)[n * 16 + l16] = r;
}

// ---------------- launch ----------------
extern "C" void kernel_launch(void* const* d_in, const int* in_sizes, int n_in,
                              void* d_out, int out_size)
{
    const float* x     = (const float*)d_in[0];
    const int*   ei    = (const int*)d_in[1];
    const float* Wl    = (const float*)d_in[2];
    const float* bl    = (const float*)d_in[3];
    const float* Wr    = (const float*)d_in[4];
    const float* br    = (const float*)d_in[5];
    const float* att   = (const float*)d_in[6];
    const float* bias  = (const float*)d_in[7];
    const float* gamma = (const float*)d_in[8];
    const float* beta  = (const float*)d_in[9];
    float* out = (float*)d_out;

    cudaFuncSetAttribute(gemm_kernel,
                         cudaFuncAttributeMaxDynamicSharedMemorySize, GEMM_SMEM);

    gemm_kernel<<<(N_NODES + GEMM_TILE - 1) / GEMM_TILE, 256, GEMM_SMEM>>>(
        x, Wl, bl, Wr, br);
    edge_kernel<<<N_EDGES / 32, 256>>>(ei, att);
    finalize_kernel<<<N_NODES / 16, 256>>>(x, bias, gamma, beta, out);
}